// round 9
// baseline (speedup 1.0000x reference)
#include <cuda_runtime.h>
#include <cuda_fp16.h>
#include <math.h>

#define N_NODES 260000
#define N_EDGES 8320000
#define N_GRAPHS 10000
#define GN 26
#define EPT 4                      // edges per thread (N_EDGES % 4 == 0)

// ---- device-global scratch ----
__device__ uint2  g_xh[N_NODES];        // x quantized to f16 (4 halves, 8B)
__device__ uint4  g_xs[N_NODES];        // accum: [sumx f16 x4 | deg f16 | 3 pad halves]
__device__ uint4  g_zh[N_NODES * 2];    // z in f16: 12 halves used, 32B stride
__device__ uint4  g_aggA[N_NODES];      // agg ch0-7, f16 accumulation (16B)
__device__ uint2  g_aggB[N_NODES];      // agg ch8-10 (+pad), f16 accumulation (8B)
__device__ float4 g_g4[N_GRAPHS];       // per-graph pooled sums

__device__ __forceinline__ void red4f(float* p, float a, float b, float c, float d) {
    asm volatile("red.global.add.v4.f32 [%0], {%1,%2,%3,%4};"
                 :: "l"(__cvta_generic_to_global(p)), "f"(a), "f"(b), "f"(c), "f"(d)
                 : "memory");
}
__device__ __forceinline__ void redh8(void* p, unsigned a, unsigned b, unsigned c, unsigned d) {
    asm volatile("red.global.add.noftz.v4.f16x2 [%0], {%1,%2,%3,%4};"
                 :: "l"(__cvta_generic_to_global(p)), "r"(a), "r"(b), "r"(c), "r"(d)
                 : "memory");
}
__device__ __forceinline__ void redh4(void* p, unsigned a, unsigned b) {
    asm volatile("red.global.add.noftz.v2.f16x2 [%0], {%1,%2};"
                 :: "l"(__cvta_generic_to_global(p)), "r"(a), "r"(b)
                 : "memory");
}
__device__ __forceinline__ unsigned packh2(float a, float b) {
    __half2 h = __floats2half2_rn(a, b);
    return *reinterpret_cast<unsigned*>(&h);
}
__device__ __forceinline__ float2 unpackh2(unsigned u) {
    __half2 h = *reinterpret_cast<__half2*>(&u);
    return __half22float2(h);
}

// ---------------- K0: init — quantize x to f16, zero accumulators ----------------
__global__ void init_kernel(const float4* __restrict__ x) {
    int i = blockIdx.x * blockDim.x + threadIdx.x;
    if (i < N_NODES) {
        float4 v = __ldg(&x[i]);
        g_xh[i] = make_uint2(packh2(v.x, v.y), packh2(v.z, v.w));
        g_xs[i] = make_uint4(0u, 0u, 0u, 0u);
    }
    if (i < N_GRAPHS) g_g4[i] = make_float4(0.f, 0.f, 0.f, 0.f);
}

// ---------------- K1: edge pass 1 — 4 edges/thread, int4 index loads, 1 RED/edge ----------------
__global__ void edge1_kernel(const int4* __restrict__ eir, const int4* __restrict__ eic) {
    int t = blockIdx.x * blockDim.x + threadIdx.x;
    if (t >= N_EDGES / EPT) return;
    int4 r4 = __ldcs(&eir[t]);
    int4 c4 = __ldcs(&eic[t]);
    uint2 v0 = __ldg(&g_xh[r4.x]);
    uint2 v1 = __ldg(&g_xh[r4.y]);
    uint2 v2 = __ldg(&g_xh[r4.z]);
    uint2 v3 = __ldg(&g_xh[r4.w]);
    // halves: [x0,x1, x2,x3, 1.0,0, 0,0] -> deg counts exactly in f16
    redh8(&g_xs[c4.x], v0.x, v0.y, 0x00003C00u, 0u);
    redh8(&g_xs[c4.y], v1.x, v1.y, 0x00003C00u, 0u);
    redh8(&g_xs[c4.z], v2.x, v2.y, 0x00003C00u, 0u);
    redh8(&g_xs[c4.w], v3.x, v3.y, 0x00003C00u, 0u);
}

// ---------------- K2: node pass 1 — h1 = tanh(...), z = h1@W2^T; seed aggs ----------------
__global__ void node1_kernel(const float4* __restrict__ x,
                             const float* __restrict__ W1,
                             const float* __restrict__ b1,
                             const float* __restrict__ W2) {
    __shared__ float sW1[26 * 4];
    __shared__ float sb1[26];
    __shared__ float sW2[11 * 26];
    int t = threadIdx.x;
    for (int i = t; i < 26 * 4; i += blockDim.x)  sW1[i] = W1[i];
    for (int i = t; i < 26; i += blockDim.x)      sb1[i] = b1[i];
    for (int i = t; i < 11 * 26; i += blockDim.x) sW2[i] = W2[i];
    __syncthreads();

    int i = blockIdx.x * blockDim.x + t;
    if (i >= N_NODES) return;

    uint4 sv = g_xs[i];
    float2 s01 = unpackh2(sv.x), s23 = unpackh2(sv.y);
    float  deg = unpackh2(sv.z).x;
    float4 xi = __ldg(&x[i]);                 // self-loop: exact f32
    float t0 = s01.x + xi.x, t1 = s01.y + xi.y;
    float t2 = s23.x + xi.z, t3 = s23.y + xi.w;
    float c1 = deg + 1.0f;

    float h[26];
#pragma unroll
    for (int j = 0; j < 26; j++) {
        float a = fmaf(sW1[j * 4 + 0], t0,
                  fmaf(sW1[j * 4 + 1], t1,
                  fmaf(sW1[j * 4 + 2], t2,
                  fmaf(sW1[j * 4 + 3], t3, c1 * sb1[j]))));
        h[j] = tanhf(a);
    }

    float z[11];
#pragma unroll
    for (int k = 0; k < 11; k++) {
        float a = 0.f;
#pragma unroll
        for (int j = 0; j < 26; j++) a = fmaf(sW2[k * 26 + j], h[j], a);
        z[k] = a;
    }

    uint4 A;
    A.x = packh2(z[0], z[1]);  A.y = packh2(z[2], z[3]);
    A.z = packh2(z[4], z[5]);  A.w = packh2(z[6], z[7]);
    uint2 B = make_uint2(packh2(z[8], z[9]), packh2(z[10], 0.f));
    g_zh[i * 2]     = A;
    g_zh[i * 2 + 1] = make_uint4(B.x, B.y, 0u, 0u);

    // seed aggs with self-loop z
    g_aggA[i] = A;
    g_aggB[i] = B;
}

// ---------------- K3: edge pass 2 — 4 edges/thread, 2 REDs/edge ----------------
__global__ void edge2_kernel(const int4* __restrict__ eir, const int4* __restrict__ eic) {
    int t = blockIdx.x * blockDim.x + threadIdx.x;
    if (t >= N_EDGES / EPT) return;
    int4 r4 = __ldcs(&eir[t]);
    int4 c4 = __ldcs(&eic[t]);

    const uint4* z0 = &g_zh[r4.x * 2];
    const uint4* z1 = &g_zh[r4.y * 2];
    const uint4* z2 = &g_zh[r4.z * 2];
    const uint4* z3 = &g_zh[r4.w * 2];
    uint4 A0 = __ldg(z0); uint2 B0 = __ldg((const uint2*)(z0 + 1));
    uint4 A1 = __ldg(z1); uint2 B1 = __ldg((const uint2*)(z1 + 1));
    uint4 A2 = __ldg(z2); uint2 B2 = __ldg((const uint2*)(z2 + 1));
    uint4 A3 = __ldg(z3); uint2 B3 = __ldg((const uint2*)(z3 + 1));

    redh8(&g_aggA[c4.x], A0.x, A0.y, A0.z, A0.w);
    redh4(&g_aggB[c4.x], B0.x, B0.y);
    redh8(&g_aggA[c4.y], A1.x, A1.y, A1.z, A1.w);
    redh4(&g_aggB[c4.y], B1.x, B1.y);
    redh8(&g_aggA[c4.z], A2.x, A2.y, A2.z, A2.w);
    redh4(&g_aggB[c4.z], B2.x, B2.y);
    redh8(&g_aggA[c4.w], A3.x, A3.y, A3.z, A3.w);
    redh4(&g_aggB[c4.w], B3.x, B3.y);
}

// ---------------- K4: node pass 2 — tanh, maxpool, graph-sum scatter ----------------
__global__ void node2_kernel(const float* __restrict__ b2) {
    __shared__ float sb2[11];
    int t = threadIdx.x;
    if (t < 11) sb2[t] = b2[t];
    __syncthreads();

    int i = blockIdx.x * blockDim.x + t;
    if (i >= N_NODES) return;

    float deg = unpackh2(g_xs[i].z).x;
    float c1 = deg + 1.0f;

    uint4 A = g_aggA[i];
    uint2 B = g_aggB[i];
    float2 a01 = unpackh2(A.x), a23 = unpackh2(A.y);
    float2 a45 = unpackh2(A.z), a67 = unpackh2(A.w);
    float2 a89 = unpackh2(B.x), aA_ = unpackh2(B.y);

    float av[11] = {a01.x, a01.y, a23.x, a23.y, a45.x, a45.y, a67.x, a67.y,
                    a89.x, a89.y, aA_.x};
    float v[11];
#pragma unroll
    for (int k = 0; k < 11; k++)
        v[k] = tanhf(av[k] + c1 * sb2[k]);

    float p0 = fmaxf(v[0], v[1]);
    float p1 = fmaxf(fmaxf(v[2], v[3]), v[4]);
    float p2 = fmaxf(fmaxf(v[5], v[6]), v[7]);
    float p3 = fmaxf(fmaxf(v[8], v[9]), v[10]);

    red4f((float*)&g_g4[i / GN], p0, p1, p2, p3);
}

// ---------------- K5: per-graph linear + softmax ----------------
__global__ void final_kernel(const float* __restrict__ Wl,
                             const float* __restrict__ bl,
                             float* __restrict__ out) {
    int g = blockIdx.x * blockDim.x + threadIdx.x;
    if (g >= N_GRAPHS) return;
    float4 gv = g_g4[g];
    float o0 = fmaf(Wl[0], gv.x, fmaf(Wl[1], gv.y, fmaf(Wl[2], gv.z, fmaf(Wl[3], gv.w, bl[0]))));
    float o1 = fmaf(Wl[4], gv.x, fmaf(Wl[5], gv.y, fmaf(Wl[6], gv.z, fmaf(Wl[7], gv.w, bl[1]))));
    float m = fmaxf(o0, o1);
    float e0 = expf(o0 - m), e1 = expf(o1 - m);
    float inv = 1.0f / (e0 + e1);
    out[g * 2 + 0] = e0 * inv;
    out[g * 2 + 1] = e1 * inv;
}

extern "C" void kernel_launch(void* const* d_in, const int* in_sizes, int n_in,
                              void* d_out, int out_size) {
    const float4* x  = (const float4*)d_in[0];   // [260000,4] f32
    const int*    ei = (const int*)d_in[1];      // [2, 8320000] i32
    const float*  W1 = (const float*)d_in[2];
    const float*  b1 = (const float*)d_in[3];
    const float*  W2 = (const float*)d_in[4];
    const float*  b2 = (const float*)d_in[5];
    const float*  Wl = (const float*)d_in[6];
    const float*  bl = (const float*)d_in[7];
    float* out = (float*)d_out;                  // [10000,2]

    const int4* eir = (const int4*)ei;               // rows
    const int4* eic = (const int4*)(ei + N_EDGES);   // cols

    const int T = 256;
    const int EB = (N_EDGES / EPT + T - 1) / T;
    const int NB = (N_NODES + T - 1) / T;

    init_kernel<<<NB, T>>>(x);
    edge1_kernel<<<EB, T>>>(eir, eic);
    node1_kernel<<<NB, T>>>(x, W1, b1, W2);
    edge2_kernel<<<EB, T>>>(eir, eic);
    node2_kernel<<<NB, T>>>(b2);
    final_kernel<<<(N_GRAPHS + T - 1) / T, T>>>(Wl, bl, out);
}

// round 10
// speedup vs baseline: 1.0146x; 1.0146x over previous
#include <cuda_runtime.h>
#include <cuda_fp16.h>
#include <math.h>

#define N_NODES 260000
#define N_EDGES 8320000
#define N_GRAPHS 10000
#define GN 26

// ---- device-global scratch ----
__device__ uint2  g_xh[N_NODES];        // x quantized to f16 (4 halves, 8B)
__device__ uint4  g_xs[N_NODES];        // accum: [sumx f16 x4 | deg f16 | 3 pad] seeded with self
__device__ uint4  g_zh[N_NODES * 2];    // z in f16: 12 halves used, 32B stride
__device__ uint4  g_aggA[N_NODES];      // agg ch0-7, f16 accumulation (16B)
__device__ uint2  g_aggB[N_NODES];      // agg ch8-10 (+pad), f16 accumulation (8B)
__device__ float4 g_g4[N_GRAPHS];       // per-graph pooled sums

__device__ __forceinline__ void red4f(float* p, float a, float b, float c, float d) {
    asm volatile("red.global.add.v4.f32 [%0], {%1,%2,%3,%4};"
                 :: "l"(__cvta_generic_to_global(p)), "f"(a), "f"(b), "f"(c), "f"(d)
                 : "memory");
}
__device__ __forceinline__ void redh8(void* p, unsigned a, unsigned b, unsigned c, unsigned d) {
    asm volatile("red.global.add.noftz.v4.f16x2 [%0], {%1,%2,%3,%4};"
                 :: "l"(__cvta_generic_to_global(p)), "r"(a), "r"(b), "r"(c), "r"(d)
                 : "memory");
}
__device__ __forceinline__ void redh4(void* p, unsigned a, unsigned b) {
    asm volatile("red.global.add.noftz.v2.f16x2 [%0], {%1,%2};"
                 :: "l"(__cvta_generic_to_global(p)), "r"(a), "r"(b)
                 : "memory");
}
__device__ __forceinline__ unsigned packh2(float a, float b) {
    __half2 h = __floats2half2_rn(a, b);
    return *reinterpret_cast<unsigned*>(&h);
}
__device__ __forceinline__ float2 unpackh2(unsigned u) {
    __half2 h = *reinterpret_cast<__half2*>(&u);
    return __half22float2(h);
}

// ---------------- K0: init — quantize x to f16; seed accumulators with self-loop ----------------
__global__ void init_kernel(const float4* __restrict__ x) {
    int i = blockIdx.x * blockDim.x + threadIdx.x;
    if (i < N_NODES) {
        float4 v = __ldg(&x[i]);
        unsigned p01 = packh2(v.x, v.y);
        unsigned p23 = packh2(v.z, v.w);
        g_xh[i] = make_uint2(p01, p23);
        // seed: sum = self x (f16), deg = 1.0 (self loop)
        g_xs[i] = make_uint4(p01, p23, 0x00003C00u, 0u);
    }
    if (i < N_GRAPHS) g_g4[i] = make_float4(0.f, 0.f, 0.f, 0.f);
}

// ---------------- K1: edge pass 1 — ONE red.v4.f16x2: [sum x (f16), deg] ----------------
__global__ void edge1_kernel(const int* __restrict__ ei) {
    int e = blockIdx.x * blockDim.x + threadIdx.x;
    if (e >= N_EDGES) return;
    int r = __ldcs(&ei[e]);
    int c = __ldcs(&ei[N_EDGES + e]);
    uint2 v = __ldg(&g_xh[r]);
    // halves: [x0,x1, x2,x3, 1.0,0, 0,0] -> deg counts exactly in f16
    redh8(&g_xs[c], v.x, v.y, 0x00003C00u, 0u);
}

// ---------------- K2: node pass 1 — h1 = tanh(...), z = h1@W2^T; seed aggs ----------------
__global__ void node1_kernel(const float* __restrict__ W1,
                             const float* __restrict__ b1,
                             const float* __restrict__ W2) {
    __shared__ float sW1[26 * 4];
    __shared__ float sb1[26];
    __shared__ float sW2[11 * 26];
    int t = threadIdx.x;
    for (int i = t; i < 26 * 4; i += blockDim.x)  sW1[i] = W1[i];
    for (int i = t; i < 26; i += blockDim.x)      sb1[i] = b1[i];
    for (int i = t; i < 11 * 26; i += blockDim.x) sW2[i] = W2[i];
    __syncthreads();

    int i = blockIdx.x * blockDim.x + t;
    if (i >= N_NODES) return;

    uint4 sv = g_xs[i];                       // self already included
    float2 s01 = unpackh2(sv.x), s23 = unpackh2(sv.y);
    float  c1  = unpackh2(sv.z).x;            // deg + 1 (self seeded)
    float t0 = s01.x, t1 = s01.y, t2 = s23.x, t3 = s23.y;

    float h[26];
#pragma unroll
    for (int j = 0; j < 26; j++) {
        float a = fmaf(sW1[j * 4 + 0], t0,
                  fmaf(sW1[j * 4 + 1], t1,
                  fmaf(sW1[j * 4 + 2], t2,
                  fmaf(sW1[j * 4 + 3], t3, c1 * sb1[j]))));
        h[j] = tanhf(a);
    }

    float z[11];
#pragma unroll
    for (int k = 0; k < 11; k++) {
        float a = 0.f;
#pragma unroll
        for (int j = 0; j < 26; j++) a = fmaf(sW2[k * 26 + j], h[j], a);
        z[k] = a;
    }

    uint4 A;
    A.x = packh2(z[0], z[1]);  A.y = packh2(z[2], z[3]);
    A.z = packh2(z[4], z[5]);  A.w = packh2(z[6], z[7]);
    uint2 B = make_uint2(packh2(z[8], z[9]), packh2(z[10], 0.f));
    g_zh[i * 2]     = A;
    g_zh[i * 2 + 1] = make_uint4(B.x, B.y, 0u, 0u);

    // seed aggs with self-loop z
    g_aggA[i] = A;
    g_aggB[i] = B;
}

// ---------------- K3: edge pass 2 — gather 1 sector + 2 f16 REDs ----------------
__global__ void edge2_kernel(const int* __restrict__ ei) {
    int e = blockIdx.x * blockDim.x + threadIdx.x;
    if (e >= N_EDGES) return;
    int r = __ldcs(&ei[e]);
    int c = __ldcs(&ei[N_EDGES + e]);

    const uint4* zp = &g_zh[r * 2];
    uint4 A = __ldg(zp);                            // ch0..7
    uint2 B = __ldg((const uint2*)(zp + 1));        // ch8..10, same 32B sector

    redh8(&g_aggA[c], A.x, A.y, A.z, A.w);
    redh4(&g_aggB[c], B.x, B.y);
}

// ---------------- K4: node pass 2 — tanh, maxpool, graph-sum scatter ----------------
__global__ void node2_kernel(const float* __restrict__ b2) {
    __shared__ float sb2[11];
    int t = threadIdx.x;
    if (t < 11) sb2[t] = b2[t];
    __syncthreads();

    int i = blockIdx.x * blockDim.x + t;
    if (i >= N_NODES) return;

    float c1 = unpackh2(g_xs[i].z).x;         // deg + 1

    uint4 A = g_aggA[i];
    uint2 B = g_aggB[i];
    float2 a01 = unpackh2(A.x), a23 = unpackh2(A.y);
    float2 a45 = unpackh2(A.z), a67 = unpackh2(A.w);
    float2 a89 = unpackh2(B.x), aA_ = unpackh2(B.y);

    float av[11] = {a01.x, a01.y, a23.x, a23.y, a45.x, a45.y, a67.x, a67.y,
                    a89.x, a89.y, aA_.x};
    float v[11];
#pragma unroll
    for (int k = 0; k < 11; k++)
        v[k] = tanhf(av[k] + c1 * sb2[k]);

    // MaxPool1d(3, stride 3, left-pad 1)
    float p0 = fmaxf(v[0], v[1]);
    float p1 = fmaxf(fmaxf(v[2], v[3]), v[4]);
    float p2 = fmaxf(fmaxf(v[5], v[6]), v[7]);
    float p3 = fmaxf(fmaxf(v[8], v[9]), v[10]);

    red4f((float*)&g_g4[i / GN], p0, p1, p2, p3);
}

// ---------------- K5: per-graph linear + softmax ----------------
__global__ void final_kernel(const float* __restrict__ Wl,
                             const float* __restrict__ bl,
                             float* __restrict__ out) {
    int g = blockIdx.x * blockDim.x + threadIdx.x;
    if (g >= N_GRAPHS) return;
    float4 gv = g_g4[g];
    float o0 = fmaf(Wl[0], gv.x, fmaf(Wl[1], gv.y, fmaf(Wl[2], gv.z, fmaf(Wl[3], gv.w, bl[0]))));
    float o1 = fmaf(Wl[4], gv.x, fmaf(Wl[5], gv.y, fmaf(Wl[6], gv.z, fmaf(Wl[7], gv.w, bl[1]))));
    float m = fmaxf(o0, o1);
    float e0 = expf(o0 - m), e1 = expf(o1 - m);
    float inv = 1.0f / (e0 + e1);
    out[g * 2 + 0] = e0 * inv;
    out[g * 2 + 1] = e1 * inv;
}

extern "C" void kernel_launch(void* const* d_in, const int* in_sizes, int n_in,
                              void* d_out, int out_size) {
    const float4* x  = (const float4*)d_in[0];   // [260000,4] f32
    const int*    ei = (const int*)d_in[1];      // [2, 8320000] i32
    const float*  W1 = (const float*)d_in[2];
    const float*  b1 = (const float*)d_in[3];
    const float*  W2 = (const float*)d_in[4];
    const float*  b2 = (const float*)d_in[5];
    const float*  Wl = (const float*)d_in[6];
    const float*  bl = (const float*)d_in[7];
    float* out = (float*)d_out;                  // [10000,2]

    const int T = 256;
    const int EB = (N_EDGES + T - 1) / T;
    const int NB = (N_NODES + T - 1) / T;

    init_kernel<<<NB, T>>>(x);
    edge1_kernel<<<EB, T>>>(ei);
    node1_kernel<<<NB, T>>>(W1, b1, W2);
    edge2_kernel<<<EB, T>>>(ei);
    node2_kernel<<<NB, T>>>(b2);
    final_kernel<<<(N_GRAPHS + T - 1) / T, T>>>(Wl, bl, out);
}

// round 11
// speedup vs baseline: 1.0283x; 1.0135x over previous
#include <cuda_runtime.h>
#include <cuda_fp16.h>
#include <math.h>

#define N_NODES 260000
#define N_EDGES 8320000
#define N_GRAPHS 10000
#define GN 26

// ---- device-global scratch (zero-initialized at module load; kernels restore
// zeros after consuming, so every graph replay re-enters a zeroed state) ----
__device__ uint4 g_xs[N_NODES];         // accum: [sum x f16 x4 | deg f16 | pad]
__device__ uint4 g_zh[N_NODES * 2];     // z in f16: 11 halves used, 32B stride
__device__ uint4 g_aggA[N_NODES];       // agg ch0-7, f16 accumulation (16B)
__device__ uint2 g_aggB[N_NODES];       // agg ch8-10 + c1 in pad lane (8B)

__device__ __forceinline__ void redh8(void* p, unsigned a, unsigned b, unsigned c, unsigned d) {
    asm volatile("red.global.add.noftz.v4.f16x2 [%0], {%1,%2,%3,%4};"
                 :: "l"(__cvta_generic_to_global(p)), "r"(a), "r"(b), "r"(c), "r"(d)
                 : "memory");
}
__device__ __forceinline__ void redh4(void* p, unsigned a, unsigned b) {
    asm volatile("red.global.add.noftz.v2.f16x2 [%0], {%1,%2};"
                 :: "l"(__cvta_generic_to_global(p)), "r"(a), "r"(b)
                 : "memory");
}
__device__ __forceinline__ unsigned packh2(float a, float b) {
    __half2 h = __floats2half2_rn(a, b);
    return *reinterpret_cast<unsigned*>(&h);
}
__device__ __forceinline__ float2 unpackh2(unsigned u) {
    __half2 h = *reinterpret_cast<__half2*>(&u);
    return __half22float2(h);
}

// ---------------- K1: edge pass 1 — gather f32 x, pack, ONE red.v4.f16x2 ----------------
__global__ void edge1_kernel(const int* __restrict__ ei, const float4* __restrict__ x) {
    int e = blockIdx.x * blockDim.x + threadIdx.x;
    if (e >= N_EDGES) return;
    int r = __ldcs(&ei[e]);
    int c = __ldcs(&ei[N_EDGES + e]);
    float4 v = __ldg(&x[r]);
    // halves: [x0,x1, x2,x3, 1.0,0, 0,0] -> deg counts exactly in f16
    redh8(&g_xs[c], packh2(v.x, v.y), packh2(v.z, v.w), 0x00003C00u, 0u);
}

// ---------------- K2: node pass 1 — consume+zero g_xs; h1=tanh, z=h1@W2^T; seed aggs ----------------
__global__ void node1_kernel(const float4* __restrict__ x,
                             const float* __restrict__ W1,
                             const float* __restrict__ b1,
                             const float* __restrict__ W2) {
    __shared__ float sW1[26 * 4];
    __shared__ float sb1[26];
    __shared__ float sW2[11 * 26];
    int t = threadIdx.x;
    for (int i = t; i < 26 * 4; i += blockDim.x)  sW1[i] = W1[i];
    for (int i = t; i < 26; i += blockDim.x)      sb1[i] = b1[i];
    for (int i = t; i < 11 * 26; i += blockDim.x) sW2[i] = W2[i];
    __syncthreads();

    int i = blockIdx.x * blockDim.x + t;
    if (i >= N_NODES) return;

    uint4 sv = g_xs[i];
    g_xs[i] = make_uint4(0u, 0u, 0u, 0u);     // restore zero state for next replay
    float2 s01 = unpackh2(sv.x), s23 = unpackh2(sv.y);
    float  deg = unpackh2(sv.z).x;
    float4 xi = __ldg(&x[i]);                 // self-loop, exact f32
    float t0 = s01.x + xi.x, t1 = s01.y + xi.y;
    float t2 = s23.x + xi.z, t3 = s23.y + xi.w;
    float c1 = deg + 1.0f;

    float h[26];
#pragma unroll
    for (int j = 0; j < 26; j++) {
        float a = fmaf(sW1[j * 4 + 0], t0,
                  fmaf(sW1[j * 4 + 1], t1,
                  fmaf(sW1[j * 4 + 2], t2,
                  fmaf(sW1[j * 4 + 3], t3, c1 * sb1[j]))));
        h[j] = tanhf(a);
    }

    float z[11];
#pragma unroll
    for (int k = 0; k < 11; k++) {
        float a = 0.f;
#pragma unroll
        for (int j = 0; j < 26; j++) a = fmaf(sW2[k * 26 + j], h[j], a);
        z[k] = a;
    }

    uint4 A;
    A.x = packh2(z[0], z[1]);  A.y = packh2(z[2], z[3]);
    A.z = packh2(z[4], z[5]);  A.w = packh2(z[6], z[7]);
    g_zh[i * 2]     = A;
    g_zh[i * 2 + 1] = make_uint4(packh2(z[8], z[9]), packh2(z[10], 0.f), 0u, 0u);

    // seed aggs with self-loop z; stash c1 in the pad lane (edge2 adds exact 0.0 there;
    // c1 is an integer <= ~2080, exact in f16 for this graph scale)
    g_aggA[i] = A;
    g_aggB[i] = make_uint2(packh2(z[8], z[9]), packh2(z[10], c1));
}

// ---------------- K3: edge pass 2 — gather 1 sector + 2 f16 REDs ----------------
__global__ void edge2_kernel(const int* __restrict__ ei) {
    int e = blockIdx.x * blockDim.x + threadIdx.x;
    if (e >= N_EDGES) return;
    int r = __ldcs(&ei[e]);
    int c = __ldcs(&ei[N_EDGES + e]);

    const uint4* zp = &g_zh[r * 2];
    uint4 A = __ldg(zp);                            // ch0..7
    uint2 B = __ldg((const uint2*)(zp + 1));        // ch8..10 + 0-pad, same 32B sector

    redh8(&g_aggA[c], A.x, A.y, A.z, A.w);
    redh4(&g_aggB[c], B.x, B.y);                    // pad lane += 0.0 (exact)
}

// ---------------- K4: warp-per-graph — tanh, maxpool, 26-node sum, linear, softmax ----------------
__global__ void node2final_kernel(const float* __restrict__ b2,
                                  const float* __restrict__ Wl,
                                  const float* __restrict__ bl,
                                  float2* __restrict__ out) {
    __shared__ float sb2[11];
    __shared__ float sWl[8];
    __shared__ float sbl[2];
    int t = threadIdx.x;
    if (t < 11) sb2[t] = b2[t];
    if (t < 8)  sWl[t] = Wl[t];
    if (t < 2)  sbl[t] = bl[t];
    __syncthreads();

    int gw   = (blockIdx.x * blockDim.x + t) >> 5;
    int lane = t & 31;
    if (gw >= N_GRAPHS) return;

    float p0 = 0.f, p1 = 0.f, p2 = 0.f, p3 = 0.f;
    if (lane < GN) {
        int i = gw * GN + lane;
        uint4 A = g_aggA[i];
        uint2 B = g_aggB[i];
        float2 a01 = unpackh2(A.x), a23 = unpackh2(A.y);
        float2 a45 = unpackh2(A.z), a67 = unpackh2(A.w);
        float2 a89 = unpackh2(B.x), aAc = unpackh2(B.y);
        float c1 = aAc.y;                      // deg + 1 (stashed by node1, exact)

        float av[11] = {a01.x, a01.y, a23.x, a23.y, a45.x, a45.y, a67.x, a67.y,
                        a89.x, a89.y, aAc.x};
        float v[11];
#pragma unroll
        for (int k = 0; k < 11; k++)
            v[k] = tanhf(av[k] + c1 * sb2[k]);

        // MaxPool1d(3, stride 3, left-pad 1)
        p0 = fmaxf(v[0], v[1]);
        p1 = fmaxf(fmaxf(v[2], v[3]), v[4]);
        p2 = fmaxf(fmaxf(v[5], v[6]), v[7]);
        p3 = fmaxf(fmaxf(v[8], v[9]), v[10]);
    }

#pragma unroll
    for (int o = 16; o > 0; o >>= 1) {
        p0 += __shfl_xor_sync(0xFFFFFFFFu, p0, o);
        p1 += __shfl_xor_sync(0xFFFFFFFFu, p1, o);
        p2 += __shfl_xor_sync(0xFFFFFFFFu, p2, o);
        p3 += __shfl_xor_sync(0xFFFFFFFFu, p3, o);
    }

    if (lane == 0) {
        float o0 = fmaf(sWl[0], p0, fmaf(sWl[1], p1, fmaf(sWl[2], p2, fmaf(sWl[3], p3, sbl[0]))));
        float o1 = fmaf(sWl[4], p0, fmaf(sWl[5], p1, fmaf(sWl[6], p2, fmaf(sWl[7], p3, sbl[1]))));
        float m = fmaxf(o0, o1);
        float e0 = expf(o0 - m), e1 = expf(o1 - m);
        float inv = 1.0f / (e0 + e1);
        out[gw] = make_float2(e0 * inv, e1 * inv);
    }
}

extern "C" void kernel_launch(void* const* d_in, const int* in_sizes, int n_in,
                              void* d_out, int out_size) {
    const float4* x  = (const float4*)d_in[0];   // [260000,4] f32
    const int*    ei = (const int*)d_in[1];      // [2, 8320000] i32
    const float*  W1 = (const float*)d_in[2];
    const float*  b1 = (const float*)d_in[3];
    const float*  W2 = (const float*)d_in[4];
    const float*  b2 = (const float*)d_in[5];
    const float*  Wl = (const float*)d_in[6];
    const float*  bl = (const float*)d_in[7];
    float2* out = (float2*)d_out;                // [10000,2]

    const int T = 256;
    const int EB = (N_EDGES + T - 1) / T;
    const int NB = (N_NODES + T - 1) / T;
    const int GB = (N_GRAPHS * 32 + T - 1) / T;

    edge1_kernel<<<EB, T>>>(ei, x);
    node1_kernel<<<NB, T>>>(x, W1, b1, W2);
    edge2_kernel<<<EB, T>>>(ei);
    node2final_kernel<<<GB, T>>>(b2, Wl, bl, out);
}

// round 12
// speedup vs baseline: 1.0477x; 1.0189x over previous
#include <cuda_runtime.h>
#include <cuda_fp16.h>
#include <math.h>

#define N_NODES 260000
#define N_EDGES 8320000
#define N_GRAPHS 10000
#define GN 26

// ---- device-global scratch (zero-initialized at module load; kernels restore
// zeros after consuming, so every graph replay re-enters a zeroed state) ----
__device__ uint4 g_xs[N_NODES];         // accum: [sum x f16 x4 | deg f16 | pad]
__device__ uint4 g_zh[N_NODES * 2];     // z in f16: 11 halves used, 32B stride
__device__ uint4 g_aggA[N_NODES];       // agg ch0-7, f16 accumulation (16B)
__device__ uint2 g_aggB[N_NODES];       // agg ch8-10 + c1 in pad lane (8B)

__device__ __forceinline__ void redh8(void* p, unsigned a, unsigned b, unsigned c, unsigned d) {
    asm volatile("red.global.add.noftz.v4.f16x2 [%0], {%1,%2,%3,%4};"
                 :: "l"(__cvta_generic_to_global(p)), "r"(a), "r"(b), "r"(c), "r"(d)
                 : "memory");
}
__device__ __forceinline__ void redh4(void* p, unsigned a, unsigned b) {
    asm volatile("red.global.add.noftz.v2.f16x2 [%0], {%1,%2};"
                 :: "l"(__cvta_generic_to_global(p)), "r"(a), "r"(b)
                 : "memory");
}
__device__ __forceinline__ unsigned packh2(float a, float b) {
    __half2 h = __floats2half2_rn(a, b);
    return *reinterpret_cast<unsigned*>(&h);
}
__device__ __forceinline__ float2 unpackh2(unsigned u) {
    __half2 h = *reinterpret_cast<__half2*>(&u);
    return __half22float2(h);
}
__device__ __forceinline__ float tanhfast(float x) {
    float y;
    asm("tanh.approx.f32 %0, %1;" : "=f"(y) : "f"(x));
    return y;
}

// ---------------- K1: edge pass 1 — gather f32 x, pack, ONE red.v4.f16x2 ----------------
__global__ void edge1_kernel(const int* __restrict__ ei, const float4* __restrict__ x) {
    int e = blockIdx.x * blockDim.x + threadIdx.x;
    if (e >= N_EDGES) return;
    int r = __ldcs(&ei[e]);
    int c = __ldcs(&ei[N_EDGES + e]);
    float4 v = __ldg(&x[r]);
    // halves: [x0,x1, x2,x3, 1.0,0, 0,0] -> deg counts exactly in f16
    redh8(&g_xs[c], packh2(v.x, v.y), packh2(v.z, v.w), 0x00003C00u, 0u);
}

// ---------------- K2: node pass 1 — consume+zero g_xs; h1=tanh, z=h1@W2^T; seed aggs ----------------
__global__ void node1_kernel(const float4* __restrict__ x,
                             const float* __restrict__ W1,
                             const float* __restrict__ b1,
                             const float* __restrict__ W2) {
    __shared__ float sW1[26 * 4];
    __shared__ float sb1[26];
    __shared__ float sW2[11 * 26];
    int t = threadIdx.x;
    for (int i = t; i < 26 * 4; i += blockDim.x)  sW1[i] = W1[i];
    for (int i = t; i < 26; i += blockDim.x)      sb1[i] = b1[i];
    for (int i = t; i < 11 * 26; i += blockDim.x) sW2[i] = W2[i];
    __syncthreads();

    int i = blockIdx.x * blockDim.x + t;
    if (i >= N_NODES) return;

    uint4 sv = g_xs[i];
    g_xs[i] = make_uint4(0u, 0u, 0u, 0u);     // restore zero state for next replay
    float2 s01 = unpackh2(sv.x), s23 = unpackh2(sv.y);
    float  deg = unpackh2(sv.z).x;
    float4 xi = __ldg(&x[i]);                 // self-loop, exact f32
    float t0 = s01.x + xi.x, t1 = s01.y + xi.y;
    float t2 = s23.x + xi.z, t3 = s23.y + xi.w;
    float c1 = deg + 1.0f;

    float h[26];
#pragma unroll
    for (int j = 0; j < 26; j++) {
        float a = fmaf(sW1[j * 4 + 0], t0,
                  fmaf(sW1[j * 4 + 1], t1,
                  fmaf(sW1[j * 4 + 2], t2,
                  fmaf(sW1[j * 4 + 3], t3, c1 * sb1[j]))));
        h[j] = tanhfast(a);
    }

    float z[11];
#pragma unroll
    for (int k = 0; k < 11; k++) {
        float a = 0.f;
#pragma unroll
        for (int j = 0; j < 26; j++) a = fmaf(sW2[k * 26 + j], h[j], a);
        z[k] = a;
    }

    uint4 A;
    A.x = packh2(z[0], z[1]);  A.y = packh2(z[2], z[3]);
    A.z = packh2(z[4], z[5]);  A.w = packh2(z[6], z[7]);
    g_zh[i * 2]     = A;
    g_zh[i * 2 + 1] = make_uint4(packh2(z[8], z[9]), packh2(z[10], 0.f), 0u, 0u);

    // seed aggs with self-loop z; stash c1 in the pad lane (edge2 adds exact 0.0 there;
    // c1 is an integer <= ~2080, exact in f16 at this graph scale)
    g_aggA[i] = A;
    g_aggB[i] = make_uint2(packh2(z[8], z[9]), packh2(z[10], c1));
}

// ---------------- K3: edge pass 2 — gather 1 sector + 2 f16 REDs ----------------
__global__ void edge2_kernel(const int* __restrict__ ei) {
    int e = blockIdx.x * blockDim.x + threadIdx.x;
    if (e >= N_EDGES) return;
    int r = __ldcs(&ei[e]);
    int c = __ldcs(&ei[N_EDGES + e]);

    const uint4* zp = &g_zh[r * 2];
    uint4 A = __ldg(zp);                            // ch0..7
    uint2 B = __ldg((const uint2*)(zp + 1));        // ch8..10 + 0-pad, same 32B sector

    redh8(&g_aggA[c], A.x, A.y, A.z, A.w);
    redh4(&g_aggB[c], B.x, B.y);                    // pad lane += 0.0 (exact)
}

// ---------------- K4: warp-per-graph — maxpool(pre-act), 4x tanh, 26-sum, linear, softmax ----------------
__global__ void node2final_kernel(const float* __restrict__ b2,
                                  const float* __restrict__ Wl,
                                  const float* __restrict__ bl,
                                  float2* __restrict__ out) {
    __shared__ float sb2[11];
    __shared__ float sWl[8];
    __shared__ float sbl[2];
    int t = threadIdx.x;
    if (t < 11) sb2[t] = b2[t];
    if (t < 8)  sWl[t] = Wl[t];
    if (t < 2)  sbl[t] = bl[t];
    __syncthreads();

    int gw   = (blockIdx.x * blockDim.x + t) >> 5;
    int lane = t & 31;
    if (gw >= N_GRAPHS) return;

    float p0 = 0.f, p1 = 0.f, p2 = 0.f, p3 = 0.f;
    if (lane < GN) {
        int i = gw * GN + lane;
        uint4 A = g_aggA[i];
        uint2 B = g_aggB[i];
        float2 a01 = unpackh2(A.x), a23 = unpackh2(A.y);
        float2 a45 = unpackh2(A.z), a67 = unpackh2(A.w);
        float2 a89 = unpackh2(B.x), aAc = unpackh2(B.y);
        float c1 = aAc.y;                      // deg + 1 (stashed by node1, exact)

        float u[11] = {a01.x, a01.y, a23.x, a23.y, a45.x, a45.y, a67.x, a67.y,
                       a89.x, a89.y, aAc.x};
#pragma unroll
        for (int k = 0; k < 11; k++)
            u[k] = fmaf(c1, sb2[k], u[k]);

        // tanh is monotonic: maxpool pre-activations, then 4 tanh (not 11)
        // MaxPool1d(3, stride 3, left-pad 1)
        p0 = tanhfast(fmaxf(u[0], u[1]));
        p1 = tanhfast(fmaxf(fmaxf(u[2], u[3]), u[4]));
        p2 = tanhfast(fmaxf(fmaxf(u[5], u[6]), u[7]));
        p3 = tanhfast(fmaxf(fmaxf(u[8], u[9]), u[10]));
    }

#pragma unroll
    for (int o = 16; o > 0; o >>= 1) {
        p0 += __shfl_xor_sync(0xFFFFFFFFu, p0, o);
        p1 += __shfl_xor_sync(0xFFFFFFFFu, p1, o);
        p2 += __shfl_xor_sync(0xFFFFFFFFu, p2, o);
        p3 += __shfl_xor_sync(0xFFFFFFFFu, p3, o);
    }

    if (lane == 0) {
        float o0 = fmaf(sWl[0], p0, fmaf(sWl[1], p1, fmaf(sWl[2], p2, fmaf(sWl[3], p3, sbl[0]))));
        float o1 = fmaf(sWl[4], p0, fmaf(sWl[5], p1, fmaf(sWl[6], p2, fmaf(sWl[7], p3, sbl[1]))));
        float m = fmaxf(o0, o1);
        float e0 = expf(o0 - m), e1 = expf(o1 - m);
        float inv = 1.0f / (e0 + e1);
        out[gw] = make_float2(e0 * inv, e1 * inv);
    }
}

extern "C" void kernel_launch(void* const* d_in, const int* in_sizes, int n_in,
                              void* d_out, int out_size) {
    const float4* x  = (const float4*)d_in[0];   // [260000,4] f32
    const int*    ei = (const int*)d_in[1];      // [2, 8320000] i32
    const float*  W1 = (const float*)d_in[2];
    const float*  b1 = (const float*)d_in[3];
    const float*  W2 = (const float*)d_in[4];
    const float*  b2 = (const float*)d_in[5];
    const float*  Wl = (const float*)d_in[6];
    const float*  bl = (const float*)d_in[7];
    float2* out = (float2*)d_out;                // [10000,2]

    const int T = 256;
    const int EB = (N_EDGES + T - 1) / T;
    const int NB = (N_NODES + T - 1) / T;
    const int GB = (N_GRAPHS * 32 + T - 1) / T;

    edge1_kernel<<<EB, T>>>(ei, x);
    node1_kernel<<<NB, T>>>(x, W1, b1, W2);
    edge2_kernel<<<EB, T>>>(ei);
    node2final_kernel<<<GB, T>>>(b2, Wl, bl, out);
}